// round 1
// baseline (speedup 1.0000x reference)
#include <cuda_runtime.h>
#include <cstdint>

#define BATCH 16384
#define DIM   1024
#define NLAY  6
#define NMC   64
#define HW    16

#define BM 128
#define BN 128
#define BK 16

// ---------------- scratch (static device globals; no cudaMalloc allowed) ----------------
__device__ float g_Wei[NLAY * DIM * 2 * DIM];     // fused [l][k][n], n<1024: We cols, else Wi cols (48MB)
__device__ float g_bei[NLAY * 2 * DIM];           // fused bias [l][be | bi]
__device__ float g_excinh[(size_t)BATCH * 2 * DIM]; // [B, 2048] exc|inh          (128MB)
__device__ float g_mc[(size_t)BATCH * DIM];         // [B, 1024]                   (64MB)
__device__ float g_lat[(size_t)BATCH * DIM];        // [B, 1024]                   (64MB)

// ---------------- weight / bias repack ----------------
// We,Wi: [L, NMC, D, H].  Packed: g_Wei[l][k][n], n=m*H+h -> We[l,m,k,h] (n<D) or Wi (n>=D)
__global__ void pack_wei_kernel(const float* __restrict__ We, const float* __restrict__ Wi) {
    size_t i = (size_t)blockIdx.x * blockDim.x + threadIdx.x;
    const size_t total = (size_t)NLAY * DIM * 2 * DIM;
    if (i >= total) return;
    int l = (int)(i / ((size_t)DIM * 2 * DIM));
    size_t r = i % ((size_t)DIM * 2 * DIM);
    int k = (int)(r / (2 * DIM));
    int n = (int)(r % (2 * DIM));
    const float* src;
    int nn;
    if (n < DIM) { src = We; nn = n; } else { src = Wi; nn = n - DIM; }
    int m = nn / HW, h = nn % HW;
    g_Wei[i] = src[(((size_t)l * NMC + m) * DIM + k) * HW + h];
}

__global__ void pack_bias_kernel(const float* __restrict__ be, const float* __restrict__ bi) {
    int i = blockIdx.x * blockDim.x + threadIdx.x;
    if (i >= NLAY * 2 * DIM) return;
    int l = i / (2 * DIM);
    int n = i % (2 * DIM);
    g_bei[i] = (n < DIM) ? be[l * DIM + n] : bi[l * DIM + (n - DIM)];
}

// ---------------- fp32 SGEMM: C = epi(A[M,K] @ W[K,N] + bias) ----------------
// EPI 0: bias            EPI 1: bias + relu            EPI 2: C += A@W + bias
template <int EPI>
__global__ __launch_bounds__(256, 2)
void sgemm_kernel(const float* __restrict__ A, const float* __restrict__ W,
                  const float* __restrict__ bias, float* __restrict__ C, int N) {
    const int K = DIM;  // 1024
    __shared__ float As[2][BK][BM];
    __shared__ float Bs[2][BK][BN];

    const int tid = threadIdx.x;
    const int bx = blockIdx.x;   // N tile
    const int by = blockIdx.y;   // M tile

    const float* Ab = A + (size_t)by * BM * K;
    const float* Wb = W + (size_t)bx * BN;

    // global-load mapping: A tile 128x16 (512 float4), B tile 16x128 (512 float4); 2 each/thread
    const int arow = tid >> 2;            // 0..63
    const int acol = (tid & 3) << 2;      // 0,4,8,12
    const int brow = tid >> 5;            // 0..7
    const int bcol = (tid & 31) << 2;     // 0..124

    const int tx = tid & 15;
    const int ty = tid >> 4;

    float acc[8][8];
#pragma unroll
    for (int i = 0; i < 8; i++)
#pragma unroll
        for (int j = 0; j < 8; j++) acc[i][j] = 0.f;

    float4 pa0, pa1, pb0, pb1;

    // prologue: tile 0
    pa0 = *(const float4*)(Ab + (size_t)arow * K + acol);
    pa1 = *(const float4*)(Ab + (size_t)(arow + 64) * K + acol);
    pb0 = *(const float4*)(Wb + (size_t)brow * N + bcol);
    pb1 = *(const float4*)(Wb + (size_t)(brow + 8) * N + bcol);
    As[0][acol + 0][arow] = pa0.x; As[0][acol + 1][arow] = pa0.y;
    As[0][acol + 2][arow] = pa0.z; As[0][acol + 3][arow] = pa0.w;
    As[0][acol + 0][arow + 64] = pa1.x; As[0][acol + 1][arow + 64] = pa1.y;
    As[0][acol + 2][arow + 64] = pa1.z; As[0][acol + 3][arow + 64] = pa1.w;
    *(float4*)&Bs[0][brow][bcol] = pb0;
    *(float4*)&Bs[0][brow + 8][bcol] = pb1;
    __syncthreads();

    const int NT = K / BK;  // 64
    for (int t = 0; t < NT; t++) {
        const int cur = t & 1;
        if (t + 1 < NT) {
            const int ko = (t + 1) * BK;
            pa0 = *(const float4*)(Ab + (size_t)arow * K + ko + acol);
            pa1 = *(const float4*)(Ab + (size_t)(arow + 64) * K + ko + acol);
            pb0 = *(const float4*)(Wb + (size_t)(ko + brow) * N + bcol);
            pb1 = *(const float4*)(Wb + (size_t)(ko + brow + 8) * N + bcol);
        }
#pragma unroll
        for (int k = 0; k < BK; k++) {
            float ar[8], br[8];
            *(float4*)&ar[0] = *(const float4*)&As[cur][k][ty * 4];
            *(float4*)&ar[4] = *(const float4*)&As[cur][k][ty * 4 + 64];
            *(float4*)&br[0] = *(const float4*)&Bs[cur][k][tx * 4];
            *(float4*)&br[4] = *(const float4*)&Bs[cur][k][tx * 4 + 64];
#pragma unroll
            for (int i = 0; i < 8; i++)
#pragma unroll
                for (int j = 0; j < 8; j++) acc[i][j] += ar[i] * br[j];
        }
        if (t + 1 < NT) {
            const int nxt = cur ^ 1;
            As[nxt][acol + 0][arow] = pa0.x; As[nxt][acol + 1][arow] = pa0.y;
            As[nxt][acol + 2][arow] = pa0.z; As[nxt][acol + 3][arow] = pa0.w;
            As[nxt][acol + 0][arow + 64] = pa1.x; As[nxt][acol + 1][arow + 64] = pa1.y;
            As[nxt][acol + 2][arow + 64] = pa1.z; As[nxt][acol + 3][arow + 64] = pa1.w;
            *(float4*)&Bs[nxt][brow][bcol] = pb0;
            *(float4*)&Bs[nxt][brow + 8][bcol] = pb1;
            __syncthreads();
        }
    }

    // epilogue
    const int row0 = by * BM + ty * 4;
    const int col0 = bx * BN + tx * 4;
#pragma unroll
    for (int ii = 0; ii < 2; ii++) {
#pragma unroll
        for (int i = 0; i < 4; i++) {
            const int r = row0 + ii * 64 + i;
            float* Crow = C + (size_t)r * N;
#pragma unroll
            for (int jj = 0; jj < 2; jj++) {
                const int c = col0 + jj * 64;
                float4 bv = *(const float4*)(bias + c);
                float4 v;
                v.x = acc[ii * 4 + i][jj * 4 + 0] + bv.x;
                v.y = acc[ii * 4 + i][jj * 4 + 1] + bv.y;
                v.z = acc[ii * 4 + i][jj * 4 + 2] + bv.z;
                v.w = acc[ii * 4 + i][jj * 4 + 3] + bv.w;
                if (EPI == 1) {
                    v.x = fmaxf(v.x, 0.f); v.y = fmaxf(v.y, 0.f);
                    v.z = fmaxf(v.z, 0.f); v.w = fmaxf(v.w, 0.f);
                } else if (EPI == 2) {
                    float4 old = *(const float4*)(Crow + c);
                    v.x += old.x; v.y += old.y; v.z += old.z; v.w += old.w;
                }
                *(float4*)(Crow + c) = v;
            }
        }
    }
}

// ---------------- minicolumn block-diag: mc = relu(exc - (inh @ Wl[m] + bl[m])) ----------------
// excinh: [B, 2048]  (exc cols 0..1023, inh cols 1024..2047)
// Wl: layer slice [NMC][H][H], bl: [NMC][H]
__global__ __launch_bounds__(256)
void mc_kernel(const float* __restrict__ excinh, const float* __restrict__ Wl,
               const float* __restrict__ bl, float* __restrict__ mc) {
    __shared__ float sW[HW * HW];
    __shared__ float sb[HW];
    const int m = blockIdx.y;
    if (threadIdx.x < HW * HW) sW[threadIdx.x] = Wl[m * HW * HW + threadIdx.x];
    if (threadIdx.x < HW)      sb[threadIdx.x] = bl[m * HW + threadIdx.x];
    __syncthreads();

    const int b = blockIdx.x * 256 + threadIdx.x;
    const float* row = excinh + (size_t)b * (2 * DIM);

    float inh[HW], exc[HW];
#pragma unroll
    for (int j = 0; j < 4; j++) {
        float4 vi = *(const float4*)(row + DIM + m * HW + j * 4);
        inh[j * 4 + 0] = vi.x; inh[j * 4 + 1] = vi.y; inh[j * 4 + 2] = vi.z; inh[j * 4 + 3] = vi.w;
        float4 ve = *(const float4*)(row + m * HW + j * 4);
        exc[j * 4 + 0] = ve.x; exc[j * 4 + 1] = ve.y; exc[j * 4 + 2] = ve.z; exc[j * 4 + 3] = ve.w;
    }

    float out[HW];
#pragma unroll
    for (int k = 0; k < HW; k++) {
        float lat = sb[k];
#pragma unroll
        for (int h = 0; h < HW; h++) lat += inh[h] * sW[h * HW + k];
        out[k] = fmaxf(exc[k] - lat, 0.f);
    }

    float* dst = mc + (size_t)b * DIM + m * HW;
#pragma unroll
    for (int j = 0; j < 4; j++) {
        float4 v;
        v.x = out[j * 4 + 0]; v.y = out[j * 4 + 1]; v.z = out[j * 4 + 2]; v.w = out[j * 4 + 3];
        *(float4*)(dst + j * 4) = v;
    }
}

// ---------------- driver ----------------
extern "C" void kernel_launch(void* const* d_in, const int* in_sizes, int n_in,
                              void* d_out, int out_size) {
    const float* x    = (const float*)d_in[0];
    const float* We   = (const float*)d_in[1];
    const float* be   = (const float*)d_in[2];
    const float* Wi   = (const float*)d_in[3];
    const float* bi   = (const float*)d_in[4];
    const float* Wl   = (const float*)d_in[5];
    const float* bl   = (const float*)d_in[6];
    const float* Wlat = (const float*)d_in[7];
    const float* blat = (const float*)d_in[8];
    const float* Wv   = (const float*)d_in[9];
    const float* bv   = (const float*)d_in[10];
    const float* Wo   = (const float*)d_in[11];
    const float* bo   = (const float*)d_in[12];
    const float* fbW  = (const float*)d_in[13];
    const float* fbb  = (const float*)d_in[14];
    float* out = (float*)d_out;

    const size_t BD = (size_t)BATCH * DIM;
    const size_t DD = (size_t)DIM * DIM;

    float* g_Wei_p;     cudaGetSymbolAddress((void**)&g_Wei_p, g_Wei);
    float* g_bei_p;     cudaGetSymbolAddress((void**)&g_bei_p, g_bei);
    float* g_excinh_p;  cudaGetSymbolAddress((void**)&g_excinh_p, g_excinh);
    float* g_mc_p;      cudaGetSymbolAddress((void**)&g_mc_p, g_mc);
    float* g_lat_p;     cudaGetSymbolAddress((void**)&g_lat_p, g_lat);

    // repack fused We|Wi weights + biases (every call: deterministic, ~15us)
    {
        size_t total = (size_t)NLAY * DIM * 2 * DIM;
        pack_wei_kernel<<<(unsigned)((total + 255) / 256), 256>>>(We, Wi);
        pack_bias_kernel<<<(NLAY * 2 * DIM + 255) / 256, 256>>>(be, bi);
    }

    dim3 blk(256);
    dim3 grid_wide(2 * DIM / BN, BATCH / BM);  // N = 2048
    dim3 grid_sq(DIM / BN, BATCH / BM);        // N = 1024
    dim3 grid_mc(BATCH / 256, NMC);

    for (int l = 0; l < NLAY; l++) {
        const float* xin = (l == 0) ? x : (out + (size_t)(l - 1) * BD);
        // exc|inh = relu(x @ Wei + bei)
        sgemm_kernel<1><<<grid_wide, blk>>>(xin, g_Wei_p + (size_t)l * DIM * 2 * DIM,
                                            g_bei_p + (size_t)l * 2 * DIM, g_excinh_p, 2 * DIM);
        // mc = relu(exc - (inh @ Wl + bl))
        mc_kernel<<<grid_mc, blk>>>(g_excinh_p, Wl + (size_t)l * NMC * HW * HW,
                                    bl + (size_t)l * NMC * HW, g_mc_p);
        // lateral = mc @ Wlat + blat
        sgemm_kernel<0><<<grid_sq, blk>>>(g_mc_p, Wlat + (size_t)l * DD, blat + (size_t)l * DIM,
                                          g_lat_p, DIM);
        // tmp = lateral @ Wv + bv   (reuse g_mc)
        sgemm_kernel<0><<<grid_sq, blk>>>(g_lat_p, Wv + (size_t)l * DD, bv + (size_t)l * DIM,
                                          g_mc_p, DIM);
        // attended = tmp @ Wo + bo  -> out[l]
        sgemm_kernel<0><<<grid_sq, blk>>>(g_mc_p, Wo + (size_t)l * DD, bo + (size_t)l * DIM,
                                          out + (size_t)l * BD, DIM);
    }

    // feedback: out[idx] += out[idx+1] @ fbW[i] + fbb[i], idx = 4..0
    for (int i = 0; i < NLAY - 1; i++) {
        int idx = NLAY - 2 - i;
        sgemm_kernel<2><<<grid_sq, blk>>>(out + (size_t)(idx + 1) * BD, fbW + (size_t)i * DD,
                                          fbb + (size_t)i * DIM, out + (size_t)idx * BD, DIM);
    }
}